// round 14
// baseline (speedup 1.0000x reference)
#include <cuda_runtime.h>
#include <cuda_bf16.h>
#include <math.h>
#include <stdint.h>

// Problem constants
#define BATCH   8
#define SEQ     4096
#define DIM     1024
#define ROWS    (BATCH * SEQ)         // 32768
#define HEADS   4
#define DHEAD   32
#define HID     128
#define NCHUNK  32
#define EPS     1e-5f
#define SCALE   0.17677669529663688f  // 32^-0.5

#define SWZ(o)  ((o) ^ (((o) >> 3) & 0x70))    // 128B-row swizzle (GEMM tiles)
#define CSWZ(o) ((o) ^ (((o) >> 4) & 0xF0))    // 256B-row swizzle (ctx tiles)

// ---------------------------------------------------------------------------
// Scratch (static device globals; allocation-free)
// ---------------------------------------------------------------------------
__device__ __align__(256) __nv_bfloat16 g_xn[(size_t)ROWS * DIM];       // 64 MB
__device__ __align__(256) __nv_bfloat16 g_q[(size_t)ROWS * HID];        // 8 MB
__device__ __align__(256) __nv_bfloat16 g_k[(size_t)ROWS * HID];        // 8 MB
__device__ __align__(256) __nv_bfloat16 g_v[(size_t)ROWS * HID];        // 8 MB
__device__ __align__(256) __nv_bfloat16 g_wqkvT[384 * DIM];             // [n][k]
__device__ __align__(256) __nv_bfloat16 g_wbT[BATCH * DIM * HID];       // [b][c][j]
__device__ float g_pctx[NCHUNK * BATCH * HEADS * DHEAD * DHEAD];
__device__ float g_pS[NCHUNK * BATCH * HID];

// ---------------------------------------------------------------------------
// PTX helpers (sm_80-era, compile for plain compute_103)
// ---------------------------------------------------------------------------
__device__ __forceinline__ uint32_t smem_to_u32(const void* p) {
    uint32_t a;
    asm("{ .reg .u64 t; cvta.to.shared.u64 t, %1; cvt.u32.u64 %0, t; }"
        : "=r"(a) : "l"(p));
    return a;
}
__device__ __forceinline__ void cp_async16(uint32_t dst, const void* src) {
    asm volatile("cp.async.cg.shared.global [%0], [%1], 16;" :: "r"(dst), "l"(src));
}
__device__ __forceinline__ void cp_commit() {
    asm volatile("cp.async.commit_group;" ::: "memory");
}
__device__ __forceinline__ void cp_wait1() {
    asm volatile("cp.async.wait_group 1;" ::: "memory");
}
__device__ __forceinline__ void ldsm_x4(uint32_t& r0, uint32_t& r1,
                                        uint32_t& r2, uint32_t& r3, uint32_t a) {
    asm volatile("ldmatrix.sync.aligned.m8n8.x4.shared.b16 {%0,%1,%2,%3}, [%4];"
        : "=r"(r0), "=r"(r1), "=r"(r2), "=r"(r3) : "r"(a));
}
__device__ __forceinline__ void ldsm_x4_t(uint32_t& r0, uint32_t& r1,
                                          uint32_t& r2, uint32_t& r3, uint32_t a) {
    asm volatile("ldmatrix.sync.aligned.m8n8.x4.trans.shared.b16 {%0,%1,%2,%3}, [%4];"
        : "=r"(r0), "=r"(r1), "=r"(r2), "=r"(r3) : "r"(a));
}
__device__ __forceinline__ void mma16816(float* d, const uint32_t* a, const uint32_t* b) {
    asm volatile("mma.sync.aligned.m16n8k16.row.col.f32.bf16.bf16.f32 "
        "{%0,%1,%2,%3}, {%4,%5,%6,%7}, {%8,%9}, {%0,%1,%2,%3};"
        : "+f"(d[0]), "+f"(d[1]), "+f"(d[2]), "+f"(d[3])
        : "r"(a[0]), "r"(a[1]), "r"(a[2]), "r"(a[3]), "r"(b[0]), "r"(b[1]));
}

// ---------------------------------------------------------------------------
// Generic HMMA GEMM body (R6 2-stage config — measured best).
// C[M,N] = A[M,K](bf16,row) @ B[N,K](bf16,K-major)^T
// ---------------------------------------------------------------------------
template<int LDA, int LDB, int KITERS, bool OUT_EPI>
__device__ __forceinline__ void gemm_body(const __nv_bfloat16* __restrict__ A,
                                          const __nv_bfloat16* __restrict__ B,
                                          float* __restrict__ C,
                                          const float* __restrict__ bias,
                                          const float* __restrict__ xres,
                                          char* smem) {
    const uint32_t sb = smem_to_u32(smem);
    const int tid = threadIdx.x;
    const int lane = tid & 31, wid = tid >> 5;
    const int wm = wid & 3, wn = wid >> 2;
    const int rowg0 = blockIdx.y * 128;
    const int ncol0 = blockIdx.x * 128;

    const int lr = tid >> 3, lc = tid & 7;

    float acc[2][8][4];
    #pragma unroll
    for (int mt = 0; mt < 2; ++mt)
        #pragma unroll
        for (int nt = 0; nt < 8; ++nt)
            #pragma unroll
            for (int i = 0; i < 4; ++i) acc[mt][nt][i] = 0.f;

    auto load_stage = [&](int it, int stage) {
        const uint32_t Ao = (uint32_t)stage * 32768u;
        const uint32_t Bo = Ao + 16384u;
        const __nv_bfloat16* As = A + (size_t)rowg0 * LDA + it * 64;
        const __nv_bfloat16* Bs = B + (size_t)ncol0 * LDB + it * 64;
        #pragma unroll
        for (int p = 0; p < 4; ++p) {
            const int r = lr + p * 32;
            cp_async16(sb + Ao + SWZ((uint32_t)(r * 128 + lc * 16)),
                       As + (size_t)r * LDA + lc * 8);
        }
        #pragma unroll
        for (int p = 0; p < 4; ++p) {
            const int r = lr + p * 32;
            cp_async16(sb + Bo + SWZ((uint32_t)(r * 128 + lc * 16)),
                       Bs + (size_t)r * LDB + lc * 8);
        }
        cp_commit();
    };

    load_stage(0, 0);

    const int a_row = ((lane >> 3) & 1) * 8 + (lane & 7);
    const int a_kh  = (lane >> 4) * 8;
    const int b_nr  = (lane >> 4) * 8 + (lane & 7);
    const int b_kh  = ((lane >> 3) & 1) * 8;

    for (int it = 0; it < KITERS; ++it) {
        if (it + 1 < KITERS) load_stage(it + 1, (it + 1) & 1);
        else cp_commit();
        cp_wait1();
        __syncthreads();

        const uint32_t Ao = sb + (uint32_t)(it & 1) * 32768u;
        const uint32_t Bo = Ao + 16384u;

        #pragma unroll
        for (int ks = 0; ks < 4; ++ks) {
            uint32_t a[2][4];
            #pragma unroll
            for (int mt = 0; mt < 2; ++mt) {
                const int row = wm * 32 + mt * 16 + a_row;
                const int kc  = ks * 16 + a_kh;
                ldsm_x4(a[mt][0], a[mt][1], a[mt][2], a[mt][3],
                        Ao + SWZ((uint32_t)(row * 128 + kc * 2)));
            }
            uint32_t b[8][2];
            #pragma unroll
            for (int np = 0; np < 4; ++np) {
                const int nr = wn * 64 + np * 16 + b_nr;
                const int kc = ks * 16 + b_kh;
                ldsm_x4(b[np * 2][0], b[np * 2][1], b[np * 2 + 1][0], b[np * 2 + 1][1],
                        Bo + SWZ((uint32_t)(nr * 128 + kc * 2)));
            }
            #pragma unroll
            for (int mt = 0; mt < 2; ++mt)
                #pragma unroll
                for (int nt = 0; nt < 8; ++nt)
                    mma16816(acc[mt][nt], a[mt], b[nt]);
        }
        __syncthreads();
    }

    if (OUT_EPI) {
        #pragma unroll
        for (int mt = 0; mt < 2; ++mt) {
            const int r0 = rowg0 + wm * 32 + mt * 16 + (lane >> 2);
            #pragma unroll
            for (int nt = 0; nt < 8; ++nt) {
                const int c = ncol0 + wn * 64 + nt * 8 + (lane & 3) * 2;
                float2 v0 = make_float2(acc[mt][nt][0], acc[mt][nt][1]);
                float2 v1 = make_float2(acc[mt][nt][2], acc[mt][nt][3]);
                const float2 bo = *(const float2*)(bias + c);
                const float2 x0 = *(const float2*)(xres + (size_t)r0 * DIM + c);
                const float2 x1 = *(const float2*)(xres + (size_t)(r0 + 8) * DIM + c);
                v0.x += bo.x + x0.x; v0.y += bo.y + x0.y;
                v1.x += bo.x + x1.x; v1.y += bo.y + x1.y;
                *(float2*)(C + (size_t)r0 * DIM + c) = v0;
                *(float2*)(C + (size_t)(r0 + 8) * DIM + c) = v1;
            }
        }
    } else {
        __nv_bfloat16* dst = (blockIdx.x == 0) ? g_q : (blockIdx.x == 1) ? g_k : g_v;
        #pragma unroll
        for (int mt = 0; mt < 2; ++mt) {
            const int r0 = rowg0 + wm * 32 + mt * 16 + (lane >> 2);
            #pragma unroll
            for (int nt = 0; nt < 8; ++nt) {
                const int c = wn * 64 + nt * 8 + (lane & 3) * 2;
                *(__nv_bfloat162*)(dst + (size_t)r0 * HID + c) =
                    __float22bfloat162_rn(make_float2(acc[mt][nt][0], acc[mt][nt][1]));
                *(__nv_bfloat162*)(dst + (size_t)(r0 + 8) * HID + c) =
                    __float22bfloat162_rn(make_float2(acc[mt][nt][2], acc[mt][nt][3]));
            }
        }
    }
}

#define GEMM_SMEM 65536   // 2 stages x 32 KB

// grid (3, 256): q/k/v = xn @ wqkvT^T   (2 blocks/SM)
__global__ __launch_bounds__(256, 2) void k_qkv_mma() {
    extern __shared__ __align__(1024) char smem[];
    gemm_body<DIM, DIM, 16, false>(g_xn, g_wqkvT, nullptr, nullptr, nullptr, smem);
}
// grid (8, 256): out = q @ Wb_b^T + b_out + x
__global__ __launch_bounds__(256, 2) void k_out_mma(const float* __restrict__ x,
                                                    const float* __restrict__ b_out,
                                                    float* __restrict__ out) {
    extern __shared__ __align__(1024) char smem[];
    const int batch = blockIdx.y >> 5;
    gemm_body<HID, HID, 2, true>(g_q, g_wbT + (size_t)batch * DIM * HID,
                                 out, b_out, x, smem);
}

// ---------------------------------------------------------------------------
// K1: LayerNorm -> bf16, with weight prep fused in the grid tail
// (blocks >= ROWS convert wqkv to bf16 K-major; runs concurrently with LN).
// grid = ROWS + 1536
// ---------------------------------------------------------------------------
__global__ __launch_bounds__(256) void k_ln(const float* __restrict__ x,
                                            const float* __restrict__ gamma,
                                            const float* __restrict__ beta,
                                            const float* __restrict__ wqkv) {
    const int tid = threadIdx.x;
    if (blockIdx.x >= ROWS) {
        const int idx = (blockIdx.x - ROWS) * 256 + tid;   // < 384*1024
        const int n = idx >> 10, k = idx & 1023;
        g_wqkvT[idx] = __float2bfloat16(wqkv[k * 384 + n]);
        return;
    }
    const int row = blockIdx.x;
    const float4 f = ((const float4*)(x + (size_t)row * DIM))[tid];

    float s  = f.x + f.y + f.z + f.w;
    float s2 = fmaf(f.x, f.x, fmaf(f.y, f.y, fmaf(f.z, f.z, f.w * f.w)));
    #pragma unroll
    for (int off = 16; off > 0; off >>= 1) {
        s  += __shfl_xor_sync(0xffffffffu, s,  off);
        s2 += __shfl_xor_sync(0xffffffffu, s2, off);
    }
    __shared__ float red[16];
    const int wid = tid >> 5, lane = tid & 31;
    if (lane == 0) { red[wid] = s; red[8 + wid] = s2; }
    __syncthreads();
    float ts = 0.f, ts2 = 0.f;
    #pragma unroll
    for (int w = 0; w < 8; ++w) { ts += red[w]; ts2 += red[8 + w]; }

    const float mean = ts * (1.0f / DIM);
    const float var  = ts2 * (1.0f / DIM) - mean * mean;
    const float rstd = rsqrtf(var + EPS);

    const float4 g  = ((const float4*)gamma)[tid];
    const float4 be = ((const float4*)beta)[tid];
    __nv_bfloat162 p0, p1;
    p0.x = __float2bfloat16((f.x - mean) * rstd * g.x + be.x);
    p0.y = __float2bfloat16((f.y - mean) * rstd * g.y + be.y);
    p1.x = __float2bfloat16((f.z - mean) * rstd * g.z + be.z);
    p1.y = __float2bfloat16((f.w - mean) * rstd * g.w + be.w);
    __nv_bfloat162* o = (__nv_bfloat162*)(g_xn + (size_t)row * DIM);
    o[tid * 2 + 0] = p0;
    o[tid * 2 + 1] = p1;
}

// ---------------------------------------------------------------------------
// K3: ctx partials via HMMA (R12 winner, unchanged).
// ---------------------------------------------------------------------------
#define CT_KS   0u
#define CT_VS   32768u
#define CT_RED  65536u
#define CT_SMEM 66560

__global__ __launch_bounds__(256, 2) void k_ctx_mma() {
    extern __shared__ __align__(1024) char smem[];
    const uint32_t sb = smem_to_u32(smem);
    const int chunk = blockIdx.x, b = blockIdx.y;
    const int tid = threadIdx.x, lane = tid & 31, wid = tid >> 5;

    const int rbase = b * SEQ + chunk * 128;

    #pragma unroll
    for (int p = 0; p < 8; ++p) {
        const int idx = tid + p * 256;
        const int r = idx >> 4, c = idx & 15;
        const size_t go = (size_t)(rbase + r) * HID + c * 8;
        const uint4 kq = *(const uint4*)(g_k + go);
        const uint32_t kw[4] = {kq.x, kq.y, kq.z, kq.w};
        uint32_t ko[4];
        #pragma unroll
        for (int i = 0; i < 4; ++i) {
            const float2 f = __bfloat1622float2(*(const __nv_bfloat162*)&kw[i]);
            const __nv_bfloat162 e2 =
                __float22bfloat162_rn(make_float2(__expf(f.x), __expf(f.y)));
            ko[i] = *(const uint32_t*)&e2;
        }
        const uint32_t o = CSWZ((uint32_t)(r * 256 + c * 16));
        *(uint4*)(smem + CT_KS + o) = make_uint4(ko[0], ko[1], ko[2], ko[3]);
        *(uint4*)(smem + CT_VS + o) = *(const uint4*)(g_v + go);
    }
    __syncthreads();

    {
        float* red = (float*)(smem + CT_RED);
        const int d = tid & 127, half = tid >> 7;
        float s = 0.f;
        #pragma unroll 4
        for (int r = half * 64; r < half * 64 + 64; ++r)
            s += __bfloat162float(*(const __nv_bfloat16*)
                     (smem + CT_KS + CSWZ((uint32_t)(r * 256 + d * 2))));
        red[half * 128 + d] = s;
    }
    __syncthreads();
    if (tid < 128)
        g_pS[chunk * (BATCH * HID) + b * HID + tid] =
            ((float*)(smem + CT_RED))[tid] + ((float*)(smem + CT_RED))[128 + tid];

    const int h  = wid >> 1;
    const int eh = (wid & 1) * 16;

    const int a_n  = ((lane >> 4) * 8) + (lane & 7);
    const int a_d0 = h * 32 + ((lane >> 3) & 1) * 8;
    const int b_n  = (((lane >> 3) & 1) * 8) + (lane & 7);
    const int b_e  = h * 32 + eh + (lane >> 4) * 8;

    float acc[2][2][4];
    #pragma unroll
    for (int mt = 0; mt < 2; ++mt)
        #pragma unroll
        for (int ng = 0; ng < 2; ++ng)
            #pragma unroll
            for (int i = 0; i < 4; ++i) acc[mt][ng][i] = 0.f;

    #pragma unroll
    for (int kt = 0; kt < 8; ++kt) {
        const int n0 = kt * 16;
        uint32_t a[2][4];
        #pragma unroll
        for (int mt = 0; mt < 2; ++mt)
            ldsm_x4_t(a[mt][0], a[mt][1], a[mt][2], a[mt][3],
                      sb + CT_KS + CSWZ((uint32_t)((n0 + a_n) * 256
                                                   + (a_d0 + mt * 16) * 2)));
        uint32_t bb[2][2];
        ldsm_x4_t(bb[0][0], bb[0][1], bb[1][0], bb[1][1],
                  sb + CT_VS + CSWZ((uint32_t)((n0 + b_n) * 256 + b_e * 2)));
        #pragma unroll
        for (int mt = 0; mt < 2; ++mt)
            #pragma unroll
            for (int ng = 0; ng < 2; ++ng)
                mma16816(acc[mt][ng], a[mt], bb[ng]);
    }

    const size_t ob = (size_t)chunk * 32768 + (size_t)b * 4096 + (size_t)h * 1024;
    #pragma unroll
    for (int mt = 0; mt < 2; ++mt) {
        const int d0 = mt * 16 + (lane >> 2);
        #pragma unroll
        for (int ng = 0; ng < 2; ++ng) {
            const int e = eh + ng * 8 + (lane & 3) * 2;
            *(float2*)(g_pctx + ob + (size_t)d0 * 32 + e) =
                make_float2(acc[mt][ng][0], acc[mt][ng][1]);
            *(float2*)(g_pctx + ob + (size_t)(d0 + 8) * 32 + e) =
                make_float2(acc[mt][ng][2], acc[mt][ng][3]);
        }
    }
}

// ---------------------------------------------------------------------------
// K5: Wb_b = Ctx_b @ w_out -> bf16 K-major [b][c][j]
// Now also performs the partials reduction inline (k_ctx_reduce deleted):
// each of the 8 c-blocks per batch redundantly reduces its batch's partials.
// ---------------------------------------------------------------------------
__global__ __launch_bounds__(256) void k_wb(const float* __restrict__ wout) {
    __shared__ float ctx_s[4096];
    __shared__ float w_s[128][128];
    __shared__ float S_s[128];

    const int tid = threadIdx.x, lane = tid & 31;
    const int b = blockIdx.x >> 3;
    const int c0 = (blockIdx.x & 7) * 128;

    // 1/S per (h,d), folded with SCALE
    if (tid < 128) {
        float S = 0.f;
        #pragma unroll
        for (int c = 0; c < NCHUNK; ++c)
            S += g_pS[c * (BATCH * HID) + b * HID + tid];
        S_s[tid] = SCALE / S;
    }
    // w_out tile
    #pragma unroll
    for (int p = 0; p < 16; ++p) {
        const int idx = tid + p * 256;
        const int r = idx >> 5, c4 = idx & 31;
        *(float4*)&w_s[r][c4 * 4] = *(const float4*)(wout + r * DIM + c0 + c4 * 4);
    }
    __syncthreads();
    // ctx reduce + normalize
    #pragma unroll
    for (int i = 0; i < 16; ++i) {
        const int o = i * 256 + tid;
        float s = 0.f;
        #pragma unroll
        for (int c = 0; c < NCHUNK; ++c)
            s += g_pctx[(size_t)c * 32768 + b * 4096 + o];
        ctx_s[o] = s * S_s[o >> 5];
    }
    __syncthreads();

    const int h = (tid >> 5) & 3;
    const int j = h * 32 + lane;
    const int cg = tid >> 7;

    float cv[32];
    #pragma unroll
    for (int e = 0; e < 32; ++e) cv[e] = ctx_s[h * 1024 + lane * 32 + e];

    for (int cc = 0; cc < 64; ++cc) {
        const int c = cg * 64 + cc;
        float a = 0.f;
        #pragma unroll
        for (int e = 0; e < 32; ++e)
            a = fmaf(cv[e], w_s[h * 32 + e][c], a);
        g_wbT[((size_t)b * DIM + c0 + c) * HID + j] = __float2bfloat16(a);
    }
}

// ---------------------------------------------------------------------------
extern "C" void kernel_launch(void* const* d_in, const int* in_sizes, int n_in,
                              void* d_out, int out_size) {
    const float* x     = (const float*)d_in[0];
    const float* gamma = (const float*)d_in[1];
    const float* beta  = (const float*)d_in[2];
    const float* wqkv  = (const float*)d_in[3];
    const float* wout  = (const float*)d_in[4];
    const float* bout  = (const float*)d_in[5];
    float* out = (float*)d_out;

    cudaFuncSetAttribute(k_qkv_mma, cudaFuncAttributeMaxDynamicSharedMemorySize, GEMM_SMEM);
    cudaFuncSetAttribute(k_out_mma, cudaFuncAttributeMaxDynamicSharedMemorySize, GEMM_SMEM);
    cudaFuncSetAttribute(k_ctx_mma, cudaFuncAttributeMaxDynamicSharedMemorySize, CT_SMEM);

    k_ln<<<ROWS + 1536, 256>>>(x, gamma, beta, wqkv);
    k_qkv_mma<<<dim3(3, 256), 256, GEMM_SMEM>>>();
    k_ctx_mma<<<dim3(NCHUNK, BATCH), 256, CT_SMEM>>>();
    k_wb<<<64, 256>>>(wout);
    k_out_mma<<<dim3(8, 256), 256, GEMM_SMEM>>>(x, bout, out);
}

// round 15
// speedup vs baseline: 1.0099x; 1.0099x over previous
#include <cuda_runtime.h>
#include <cuda_bf16.h>
#include <math.h>
#include <stdint.h>

// Problem constants
#define BATCH   8
#define SEQ     4096
#define DIM     1024
#define ROWS    (BATCH * SEQ)         // 32768
#define HEADS   4
#define DHEAD   32
#define HID     128
#define NCHUNK  32
#define EPS     1e-5f
#define SCALE   0.17677669529663688f  // 32^-0.5

#define SWZ(o)  ((o) ^ (((o) >> 3) & 0x70))    // 128B-row swizzle (GEMM tiles)
#define CSWZ(o) ((o) ^ (((o) >> 4) & 0xF0))    // 256B-row swizzle (ctx tiles)

// ---------------------------------------------------------------------------
// Scratch (static device globals; allocation-free)
// ---------------------------------------------------------------------------
__device__ __align__(256) __nv_bfloat16 g_xn[(size_t)ROWS * DIM];       // 64 MB
__device__ __align__(256) __nv_bfloat16 g_q[(size_t)ROWS * HID];        // 8 MB
__device__ __align__(256) __nv_bfloat16 g_k[(size_t)ROWS * HID];        // 8 MB
__device__ __align__(256) __nv_bfloat16 g_v[(size_t)ROWS * HID];        // 8 MB
__device__ __align__(256) __nv_bfloat16 g_wqkvT[384 * DIM];             // [n][k]
__device__ __align__(256) __nv_bfloat16 g_wbT[BATCH * DIM * HID];       // [b][c][j]
__device__ float g_pctx[NCHUNK * BATCH * HEADS * DHEAD * DHEAD];
__device__ float g_pS[NCHUNK * BATCH * HID];
__device__ float g_ctx[BATCH * HEADS * DHEAD * DHEAD];

// ---------------------------------------------------------------------------
// PTX helpers (sm_80-era, compile for plain compute_103)
// ---------------------------------------------------------------------------
__device__ __forceinline__ uint32_t smem_to_u32(const void* p) {
    uint32_t a;
    asm("{ .reg .u64 t; cvta.to.shared.u64 t, %1; cvt.u32.u64 %0, t; }"
        : "=r"(a) : "l"(p));
    return a;
}
__device__ __forceinline__ void cp_async16(uint32_t dst, const void* src) {
    asm volatile("cp.async.cg.shared.global [%0], [%1], 16;" :: "r"(dst), "l"(src));
}
__device__ __forceinline__ void cp_commit() {
    asm volatile("cp.async.commit_group;" ::: "memory");
}
__device__ __forceinline__ void cp_wait1() {
    asm volatile("cp.async.wait_group 1;" ::: "memory");
}
__device__ __forceinline__ void ldsm_x4(uint32_t& r0, uint32_t& r1,
                                        uint32_t& r2, uint32_t& r3, uint32_t a) {
    asm volatile("ldmatrix.sync.aligned.m8n8.x4.shared.b16 {%0,%1,%2,%3}, [%4];"
        : "=r"(r0), "=r"(r1), "=r"(r2), "=r"(r3) : "r"(a));
}
__device__ __forceinline__ void ldsm_x4_t(uint32_t& r0, uint32_t& r1,
                                          uint32_t& r2, uint32_t& r3, uint32_t a) {
    asm volatile("ldmatrix.sync.aligned.m8n8.x4.trans.shared.b16 {%0,%1,%2,%3}, [%4];"
        : "=r"(r0), "=r"(r1), "=r"(r2), "=r"(r3) : "r"(a));
}
__device__ __forceinline__ void mma16816(float* d, const uint32_t* a, const uint32_t* b) {
    asm volatile("mma.sync.aligned.m16n8k16.row.col.f32.bf16.bf16.f32 "
        "{%0,%1,%2,%3}, {%4,%5,%6,%7}, {%8,%9}, {%0,%1,%2,%3};"
        : "+f"(d[0]), "+f"(d[1]), "+f"(d[2]), "+f"(d[3])
        : "r"(a[0]), "r"(a[1]), "r"(a[2]), "r"(a[3]), "r"(b[0]), "r"(b[1]));
}

// ---------------------------------------------------------------------------
// Generic HMMA GEMM body (R6 2-stage config — measured best).
// C[M,N] = A[M,K](bf16,row) @ B[N,K](bf16,K-major)^T
// ---------------------------------------------------------------------------
template<int LDA, int LDB, int KITERS, bool OUT_EPI>
__device__ __forceinline__ void gemm_body(const __nv_bfloat16* __restrict__ A,
                                          const __nv_bfloat16* __restrict__ B,
                                          float* __restrict__ C,
                                          const float* __restrict__ bias,
                                          const float* __restrict__ xres,
                                          char* smem) {
    const uint32_t sb = smem_to_u32(smem);
    const int tid = threadIdx.x;
    const int lane = tid & 31, wid = tid >> 5;
    const int wm = wid & 3, wn = wid >> 2;
    const int rowg0 = blockIdx.y * 128;
    const int ncol0 = blockIdx.x * 128;

    const int lr = tid >> 3, lc = tid & 7;

    float acc[2][8][4];
    #pragma unroll
    for (int mt = 0; mt < 2; ++mt)
        #pragma unroll
        for (int nt = 0; nt < 8; ++nt)
            #pragma unroll
            for (int i = 0; i < 4; ++i) acc[mt][nt][i] = 0.f;

    auto load_stage = [&](int it, int stage) {
        const uint32_t Ao = (uint32_t)stage * 32768u;
        const uint32_t Bo = Ao + 16384u;
        const __nv_bfloat16* As = A + (size_t)rowg0 * LDA + it * 64;
        const __nv_bfloat16* Bs = B + (size_t)ncol0 * LDB + it * 64;
        #pragma unroll
        for (int p = 0; p < 4; ++p) {
            const int r = lr + p * 32;
            cp_async16(sb + Ao + SWZ((uint32_t)(r * 128 + lc * 16)),
                       As + (size_t)r * LDA + lc * 8);
        }
        #pragma unroll
        for (int p = 0; p < 4; ++p) {
            const int r = lr + p * 32;
            cp_async16(sb + Bo + SWZ((uint32_t)(r * 128 + lc * 16)),
                       Bs + (size_t)r * LDB + lc * 8);
        }
        cp_commit();
    };

    load_stage(0, 0);

    const int a_row = ((lane >> 3) & 1) * 8 + (lane & 7);
    const int a_kh  = (lane >> 4) * 8;
    const int b_nr  = (lane >> 4) * 8 + (lane & 7);
    const int b_kh  = ((lane >> 3) & 1) * 8;

    for (int it = 0; it < KITERS; ++it) {
        if (it + 1 < KITERS) load_stage(it + 1, (it + 1) & 1);
        else cp_commit();
        cp_wait1();
        __syncthreads();

        const uint32_t Ao = sb + (uint32_t)(it & 1) * 32768u;
        const uint32_t Bo = Ao + 16384u;

        #pragma unroll
        for (int ks = 0; ks < 4; ++ks) {
            uint32_t a[2][4];
            #pragma unroll
            for (int mt = 0; mt < 2; ++mt) {
                const int row = wm * 32 + mt * 16 + a_row;
                const int kc  = ks * 16 + a_kh;
                ldsm_x4(a[mt][0], a[mt][1], a[mt][2], a[mt][3],
                        Ao + SWZ((uint32_t)(row * 128 + kc * 2)));
            }
            uint32_t b[8][2];
            #pragma unroll
            for (int np = 0; np < 4; ++np) {
                const int nr = wn * 64 + np * 16 + b_nr;
                const int kc = ks * 16 + b_kh;
                ldsm_x4(b[np * 2][0], b[np * 2][1], b[np * 2 + 1][0], b[np * 2 + 1][1],
                        Bo + SWZ((uint32_t)(nr * 128 + kc * 2)));
            }
            #pragma unroll
            for (int mt = 0; mt < 2; ++mt)
                #pragma unroll
                for (int nt = 0; nt < 8; ++nt)
                    mma16816(acc[mt][nt], a[mt], b[nt]);
        }
        __syncthreads();
    }

    if (OUT_EPI) {
        #pragma unroll
        for (int mt = 0; mt < 2; ++mt) {
            const int r0 = rowg0 + wm * 32 + mt * 16 + (lane >> 2);
            #pragma unroll
            for (int nt = 0; nt < 8; ++nt) {
                const int c = ncol0 + wn * 64 + nt * 8 + (lane & 3) * 2;
                float2 v0 = make_float2(acc[mt][nt][0], acc[mt][nt][1]);
                float2 v1 = make_float2(acc[mt][nt][2], acc[mt][nt][3]);
                const float2 bo = *(const float2*)(bias + c);
                const float2 x0 = *(const float2*)(xres + (size_t)r0 * DIM + c);
                const float2 x1 = *(const float2*)(xres + (size_t)(r0 + 8) * DIM + c);
                v0.x += bo.x + x0.x; v0.y += bo.y + x0.y;
                v1.x += bo.x + x1.x; v1.y += bo.y + x1.y;
                *(float2*)(C + (size_t)r0 * DIM + c) = v0;
                *(float2*)(C + (size_t)(r0 + 8) * DIM + c) = v1;
            }
        }
    } else {
        __nv_bfloat16* dst = (blockIdx.x == 0) ? g_q : (blockIdx.x == 1) ? g_k : g_v;
        #pragma unroll
        for (int mt = 0; mt < 2; ++mt) {
            const int r0 = rowg0 + wm * 32 + mt * 16 + (lane >> 2);
            #pragma unroll
            for (int nt = 0; nt < 8; ++nt) {
                const int c = wn * 64 + nt * 8 + (lane & 3) * 2;
                *(__nv_bfloat162*)(dst + (size_t)r0 * HID + c) =
                    __float22bfloat162_rn(make_float2(acc[mt][nt][0], acc[mt][nt][1]));
                *(__nv_bfloat162*)(dst + (size_t)(r0 + 8) * HID + c) =
                    __float22bfloat162_rn(make_float2(acc[mt][nt][2], acc[mt][nt][3]));
            }
        }
    }
}

#define GEMM_SMEM 65536   // 2 stages x 32 KB

// grid (3, 256): q/k/v = xn @ wqkvT^T   (2 blocks/SM)
__global__ __launch_bounds__(256, 2) void k_qkv_mma() {
    extern __shared__ __align__(1024) char smem[];
    gemm_body<DIM, DIM, 16, false>(g_xn, g_wqkvT, nullptr, nullptr, nullptr, smem);
}
// grid (8, 256): out = q @ Wb_b^T + b_out + x
__global__ __launch_bounds__(256, 2) void k_out_mma(const float* __restrict__ x,
                                                    const float* __restrict__ b_out,
                                                    float* __restrict__ out) {
    extern __shared__ __align__(1024) char smem[];
    const int batch = blockIdx.y >> 5;
    gemm_body<HID, HID, 2, true>(g_q, g_wbT + (size_t)batch * DIM * HID,
                                 out, b_out, x, smem);
}

// ---------------------------------------------------------------------------
// K1: LayerNorm -> bf16, with weight prep fused in the grid tail
// (blocks >= ROWS convert wqkv to bf16 K-major; runs concurrently with LN).
// grid = ROWS + 1536
// ---------------------------------------------------------------------------
__global__ __launch_bounds__(256) void k_ln(const float* __restrict__ x,
                                            const float* __restrict__ gamma,
                                            const float* __restrict__ beta,
                                            const float* __restrict__ wqkv) {
    const int tid = threadIdx.x;
    if (blockIdx.x >= ROWS) {
        const int idx = (blockIdx.x - ROWS) * 256 + tid;   // < 384*1024
        const int n = idx >> 10, k = idx & 1023;
        g_wqkvT[idx] = __float2bfloat16(wqkv[k * 384 + n]);
        return;
    }
    const int row = blockIdx.x;
    const float4 f = ((const float4*)(x + (size_t)row * DIM))[tid];

    float s  = f.x + f.y + f.z + f.w;
    float s2 = fmaf(f.x, f.x, fmaf(f.y, f.y, fmaf(f.z, f.z, f.w * f.w)));
    #pragma unroll
    for (int off = 16; off > 0; off >>= 1) {
        s  += __shfl_xor_sync(0xffffffffu, s,  off);
        s2 += __shfl_xor_sync(0xffffffffu, s2, off);
    }
    __shared__ float red[16];
    const int wid = tid >> 5, lane = tid & 31;
    if (lane == 0) { red[wid] = s; red[8 + wid] = s2; }
    __syncthreads();
    float ts = 0.f, ts2 = 0.f;
    #pragma unroll
    for (int w = 0; w < 8; ++w) { ts += red[w]; ts2 += red[8 + w]; }

    const float mean = ts * (1.0f / DIM);
    const float var  = ts2 * (1.0f / DIM) - mean * mean;
    const float rstd = rsqrtf(var + EPS);

    const float4 g  = ((const float4*)gamma)[tid];
    const float4 be = ((const float4*)beta)[tid];
    __nv_bfloat162 p0, p1;
    p0.x = __float2bfloat16((f.x - mean) * rstd * g.x + be.x);
    p0.y = __float2bfloat16((f.y - mean) * rstd * g.y + be.y);
    p1.x = __float2bfloat16((f.z - mean) * rstd * g.z + be.z);
    p1.y = __float2bfloat16((f.w - mean) * rstd * g.w + be.w);
    __nv_bfloat162* o = (__nv_bfloat162*)(g_xn + (size_t)row * DIM);
    o[tid * 2 + 0] = p0;
    o[tid * 2 + 1] = p1;
}

// ---------------------------------------------------------------------------
// K3: ctx partials via HMMA (R12 winner, unchanged).
// ---------------------------------------------------------------------------
#define CT_KS   0u
#define CT_VS   32768u
#define CT_RED  65536u
#define CT_SMEM 66560

__global__ __launch_bounds__(256, 2) void k_ctx_mma() {
    extern __shared__ __align__(1024) char smem[];
    const uint32_t sb = smem_to_u32(smem);
    const int chunk = blockIdx.x, b = blockIdx.y;
    const int tid = threadIdx.x, lane = tid & 31, wid = tid >> 5;

    const int rbase = b * SEQ + chunk * 128;

    #pragma unroll
    for (int p = 0; p < 8; ++p) {
        const int idx = tid + p * 256;
        const int r = idx >> 4, c = idx & 15;
        const size_t go = (size_t)(rbase + r) * HID + c * 8;
        const uint4 kq = *(const uint4*)(g_k + go);
        const uint32_t kw[4] = {kq.x, kq.y, kq.z, kq.w};
        uint32_t ko[4];
        #pragma unroll
        for (int i = 0; i < 4; ++i) {
            const float2 f = __bfloat1622float2(*(const __nv_bfloat162*)&kw[i]);
            const __nv_bfloat162 e2 =
                __float22bfloat162_rn(make_float2(__expf(f.x), __expf(f.y)));
            ko[i] = *(const uint32_t*)&e2;
        }
        const uint32_t o = CSWZ((uint32_t)(r * 256 + c * 16));
        *(uint4*)(smem + CT_KS + o) = make_uint4(ko[0], ko[1], ko[2], ko[3]);
        *(uint4*)(smem + CT_VS + o) = *(const uint4*)(g_v + go);
    }
    __syncthreads();

    {
        float* red = (float*)(smem + CT_RED);
        const int d = tid & 127, half = tid >> 7;
        float s = 0.f;
        #pragma unroll 4
        for (int r = half * 64; r < half * 64 + 64; ++r)
            s += __bfloat162float(*(const __nv_bfloat16*)
                     (smem + CT_KS + CSWZ((uint32_t)(r * 256 + d * 2))));
        red[half * 128 + d] = s;
    }
    __syncthreads();
    if (tid < 128)
        g_pS[chunk * (BATCH * HID) + b * HID + tid] =
            ((float*)(smem + CT_RED))[tid] + ((float*)(smem + CT_RED))[128 + tid];

    const int h  = wid >> 1;
    const int eh = (wid & 1) * 16;

    const int a_n  = ((lane >> 4) * 8) + (lane & 7);
    const int a_d0 = h * 32 + ((lane >> 3) & 1) * 8;
    const int b_n  = (((lane >> 3) & 1) * 8) + (lane & 7);
    const int b_e  = h * 32 + eh + (lane >> 4) * 8;

    float acc[2][2][4];
    #pragma unroll
    for (int mt = 0; mt < 2; ++mt)
        #pragma unroll
        for (int ng = 0; ng < 2; ++ng)
            #pragma unroll
            for (int i = 0; i < 4; ++i) acc[mt][ng][i] = 0.f;

    #pragma unroll
    for (int kt = 0; kt < 8; ++kt) {
        const int n0 = kt * 16;
        uint32_t a[2][4];
        #pragma unroll
        for (int mt = 0; mt < 2; ++mt)
            ldsm_x4_t(a[mt][0], a[mt][1], a[mt][2], a[mt][3],
                      sb + CT_KS + CSWZ((uint32_t)((n0 + a_n) * 256
                                                   + (a_d0 + mt * 16) * 2)));
        uint32_t bb[2][2];
        ldsm_x4_t(bb[0][0], bb[0][1], bb[1][0], bb[1][1],
                  sb + CT_VS + CSWZ((uint32_t)((n0 + b_n) * 256 + b_e * 2)));
        #pragma unroll
        for (int mt = 0; mt < 2; ++mt)
            #pragma unroll
            for (int ng = 0; ng < 2; ++ng)
                mma16816(acc[mt][ng], a[mt], bb[ng]);
    }

    const size_t ob = (size_t)chunk * 32768 + (size_t)b * 4096 + (size_t)h * 1024;
    #pragma unroll
    for (int mt = 0; mt < 2; ++mt) {
        const int d0 = mt * 16 + (lane >> 2);
        #pragma unroll
        for (int ng = 0; ng < 2; ++ng) {
            const int e = eh + ng * 8 + (lane & 3) * 2;
            *(float2*)(g_pctx + ob + (size_t)d0 * 32 + e) =
                make_float2(acc[mt][ng][0], acc[mt][ng][1]);
            *(float2*)(g_pctx + ob + (size_t)(d0 + 8) * 32 + e) =
                make_float2(acc[mt][ng][2], acc[mt][ng][3]);
        }
    }
}

// ---------------------------------------------------------------------------
// K4: reduce partials (grid 128 x 256 — full chip, each partial read once)
// ---------------------------------------------------------------------------
__global__ __launch_bounds__(256) void k_ctx_reduce() {
    const int o  = blockIdx.x * 256 + threadIdx.x;
    const int bi = o >> 12;
    const int hd = (o >> 5) & 127;
    float s = 0.f, S = 0.f;
    #pragma unroll
    for (int c = 0; c < NCHUNK; ++c) {
        s += g_pctx[(size_t)c * 32768 + o];
        S += g_pS[c * (BATCH * HID) + bi * HID + hd];
    }
    g_ctx[o] = s * SCALE / S;
}

// ---------------------------------------------------------------------------
// K5: Wb_b = Ctx_b @ w_out -> bf16 K-major [b][c][j]   (R12 version)
// ---------------------------------------------------------------------------
__global__ __launch_bounds__(256) void k_wb(const float* __restrict__ wout) {
    __shared__ float ctx_s[4096];
    __shared__ float w_s[128][128];

    const int tid = threadIdx.x, lane = tid & 31;
    const int b = blockIdx.x >> 3;
    const int c0 = (blockIdx.x & 7) * 128;

    #pragma unroll
    for (int i = 0; i < 16; ++i)
        ctx_s[i * 256 + tid] = g_ctx[b * 4096 + i * 256 + tid];
    #pragma unroll
    for (int p = 0; p < 16; ++p) {
        const int idx = tid + p * 256;
        const int r = idx >> 5, c4 = idx & 31;
        *(float4*)&w_s[r][c4 * 4] = *(const float4*)(wout + r * DIM + c0 + c4 * 4);
    }
    __syncthreads();

    const int h = (tid >> 5) & 3;
    const int j = h * 32 + lane;
    const int cg = tid >> 7;

    float cv[32];
    #pragma unroll
    for (int e = 0; e < 32; ++e) cv[e] = ctx_s[h * 1024 + lane * 32 + e];

    for (int cc = 0; cc < 64; ++cc) {
        const int c = cg * 64 + cc;
        float a = 0.f;
        #pragma unroll
        for (int e = 0; e < 32; ++e)
            a = fmaf(cv[e], w_s[h * 32 + e][c], a);
        g_wbT[((size_t)b * DIM + c0 + c) * HID + j] = __float2bfloat16(a);
    }
}

// ---------------------------------------------------------------------------
extern "C" void kernel_launch(void* const* d_in, const int* in_sizes, int n_in,
                              void* d_out, int out_size) {
    const float* x     = (const float*)d_in[0];
    const float* gamma = (const float*)d_in[1];
    const float* beta  = (const float*)d_in[2];
    const float* wqkv  = (const float*)d_in[3];
    const float* wout  = (const float*)d_in[4];
    const float* bout  = (const float*)d_in[5];
    float* out = (float*)d_out;

    cudaFuncSetAttribute(k_qkv_mma, cudaFuncAttributeMaxDynamicSharedMemorySize, GEMM_SMEM);
    cudaFuncSetAttribute(k_out_mma, cudaFuncAttributeMaxDynamicSharedMemorySize, GEMM_SMEM);
    cudaFuncSetAttribute(k_ctx_mma, cudaFuncAttributeMaxDynamicSharedMemorySize, CT_SMEM);

    k_ln<<<ROWS + 1536, 256>>>(x, gamma, beta, wqkv);
    k_qkv_mma<<<dim3(3, 256), 256, GEMM_SMEM>>>();
    k_ctx_mma<<<dim3(NCHUNK, BATCH), 256, CT_SMEM>>>();
    k_ctx_reduce<<<128, 256>>>();
    k_wb<<<64, 256>>>(wout);
    k_out_mma<<<dim3(8, 256), 256, GEMM_SMEM>>>(x, bout, out);
}

// round 16
// speedup vs baseline: 1.0291x; 1.0190x over previous
#include <cuda_runtime.h>
#include <cuda_bf16.h>
#include <math.h>
#include <stdint.h>

// Problem constants
#define BATCH   8
#define SEQ     4096
#define DIM     1024
#define ROWS    (BATCH * SEQ)         // 32768
#define HEADS   4
#define DHEAD   32
#define HID     128
#define NCHUNK  32
#define EPS     1e-5f
#define SCALE   0.17677669529663688f  // 32^-0.5

#define SWZ(o)  ((o) ^ (((o) >> 3) & 0x70))    // 128B-row swizzle (GEMM tiles)
#define CSWZ(o) ((o) ^ (((o) >> 4) & 0xF0))    // 256B-row swizzle (ctx tiles)

// ---------------------------------------------------------------------------
// Scratch (static device globals; allocation-free)
// ---------------------------------------------------------------------------
__device__ __align__(256) __nv_bfloat16 g_xn[(size_t)ROWS * DIM];       // 64 MB
__device__ __align__(256) __nv_bfloat16 g_q[(size_t)ROWS * HID];        // 8 MB
__device__ __align__(256) __nv_bfloat16 g_k[(size_t)ROWS * HID];        // 8 MB
__device__ __align__(256) __nv_bfloat16 g_v[(size_t)ROWS * HID];        // 8 MB
__device__ __align__(256) __nv_bfloat16 g_wqkvT[384 * DIM];             // [n][k]
__device__ __align__(256) __nv_bfloat16 g_wbT[BATCH * DIM * HID];       // [b][c][j]
__device__ float g_pctx[NCHUNK * BATCH * HEADS * DHEAD * DHEAD];        // 4 MB
__device__ float g_pS[NCHUNK * BATCH * HID];
__device__ float g_pctx_r[4 * BATCH * HEADS * DHEAD * DHEAD];           // 512 KB
__device__ float g_pS_r[4 * BATCH * HID];

// ---------------------------------------------------------------------------
// PTX helpers (sm_80-era, compile for plain compute_103)
// ---------------------------------------------------------------------------
__device__ __forceinline__ uint32_t smem_to_u32(const void* p) {
    uint32_t a;
    asm("{ .reg .u64 t; cvta.to.shared.u64 t, %1; cvt.u32.u64 %0, t; }"
        : "=r"(a) : "l"(p));
    return a;
}
__device__ __forceinline__ void cp_async16(uint32_t dst, const void* src) {
    asm volatile("cp.async.cg.shared.global [%0], [%1], 16;" :: "r"(dst), "l"(src));
}
__device__ __forceinline__ void cp_commit() {
    asm volatile("cp.async.commit_group;" ::: "memory");
}
__device__ __forceinline__ void cp_wait1() {
    asm volatile("cp.async.wait_group 1;" ::: "memory");
}
__device__ __forceinline__ void ldsm_x4(uint32_t& r0, uint32_t& r1,
                                        uint32_t& r2, uint32_t& r3, uint32_t a) {
    asm volatile("ldmatrix.sync.aligned.m8n8.x4.shared.b16 {%0,%1,%2,%3}, [%4];"
        : "=r"(r0), "=r"(r1), "=r"(r2), "=r"(r3) : "r"(a));
}
__device__ __forceinline__ void ldsm_x4_t(uint32_t& r0, uint32_t& r1,
                                          uint32_t& r2, uint32_t& r3, uint32_t a) {
    asm volatile("ldmatrix.sync.aligned.m8n8.x4.trans.shared.b16 {%0,%1,%2,%3}, [%4];"
        : "=r"(r0), "=r"(r1), "=r"(r2), "=r"(r3) : "r"(a));
}
__device__ __forceinline__ void mma16816(float* d, const uint32_t* a, const uint32_t* b) {
    asm volatile("mma.sync.aligned.m16n8k16.row.col.f32.bf16.bf16.f32 "
        "{%0,%1,%2,%3}, {%4,%5,%6,%7}, {%8,%9}, {%0,%1,%2,%3};"
        : "+f"(d[0]), "+f"(d[1]), "+f"(d[2]), "+f"(d[3])
        : "r"(a[0]), "r"(a[1]), "r"(a[2]), "r"(a[3]), "r"(b[0]), "r"(b[1]));
}

// ---------------------------------------------------------------------------
// Generic HMMA GEMM body (R6 2-stage config — measured best).
// C[M,N] = A[M,K](bf16,row) @ B[N,K](bf16,K-major)^T
// ---------------------------------------------------------------------------
template<int LDA, int LDB, int KITERS, bool OUT_EPI>
__device__ __forceinline__ void gemm_body(const __nv_bfloat16* __restrict__ A,
                                          const __nv_bfloat16* __restrict__ B,
                                          float* __restrict__ C,
                                          const float* __restrict__ bias,
                                          const float* __restrict__ xres,
                                          char* smem) {
    const uint32_t sb = smem_to_u32(smem);
    const int tid = threadIdx.x;
    const int lane = tid & 31, wid = tid >> 5;
    const int wm = wid & 3, wn = wid >> 2;
    const int rowg0 = blockIdx.y * 128;
    const int ncol0 = blockIdx.x * 128;

    const int lr = tid >> 3, lc = tid & 7;

    float acc[2][8][4];
    #pragma unroll
    for (int mt = 0; mt < 2; ++mt)
        #pragma unroll
        for (int nt = 0; nt < 8; ++nt)
            #pragma unroll
            for (int i = 0; i < 4; ++i) acc[mt][nt][i] = 0.f;

    auto load_stage = [&](int it, int stage) {
        const uint32_t Ao = (uint32_t)stage * 32768u;
        const uint32_t Bo = Ao + 16384u;
        const __nv_bfloat16* As = A + (size_t)rowg0 * LDA + it * 64;
        const __nv_bfloat16* Bs = B + (size_t)ncol0 * LDB + it * 64;
        #pragma unroll
        for (int p = 0; p < 4; ++p) {
            const int r = lr + p * 32;
            cp_async16(sb + Ao + SWZ((uint32_t)(r * 128 + lc * 16)),
                       As + (size_t)r * LDA + lc * 8);
        }
        #pragma unroll
        for (int p = 0; p < 4; ++p) {
            const int r = lr + p * 32;
            cp_async16(sb + Bo + SWZ((uint32_t)(r * 128 + lc * 16)),
                       Bs + (size_t)r * LDB + lc * 8);
        }
        cp_commit();
    };

    load_stage(0, 0);

    const int a_row = ((lane >> 3) & 1) * 8 + (lane & 7);
    const int a_kh  = (lane >> 4) * 8;
    const int b_nr  = (lane >> 4) * 8 + (lane & 7);
    const int b_kh  = ((lane >> 3) & 1) * 8;

    for (int it = 0; it < KITERS; ++it) {
        if (it + 1 < KITERS) load_stage(it + 1, (it + 1) & 1);
        else cp_commit();
        cp_wait1();
        __syncthreads();

        const uint32_t Ao = sb + (uint32_t)(it & 1) * 32768u;
        const uint32_t Bo = Ao + 16384u;

        #pragma unroll
        for (int ks = 0; ks < 4; ++ks) {
            uint32_t a[2][4];
            #pragma unroll
            for (int mt = 0; mt < 2; ++mt) {
                const int row = wm * 32 + mt * 16 + a_row;
                const int kc  = ks * 16 + a_kh;
                ldsm_x4(a[mt][0], a[mt][1], a[mt][2], a[mt][3],
                        Ao + SWZ((uint32_t)(row * 128 + kc * 2)));
            }
            uint32_t b[8][2];
            #pragma unroll
            for (int np = 0; np < 4; ++np) {
                const int nr = wn * 64 + np * 16 + b_nr;
                const int kc = ks * 16 + b_kh;
                ldsm_x4(b[np * 2][0], b[np * 2][1], b[np * 2 + 1][0], b[np * 2 + 1][1],
                        Bo + SWZ((uint32_t)(nr * 128 + kc * 2)));
            }
            #pragma unroll
            for (int mt = 0; mt < 2; ++mt)
                #pragma unroll
                for (int nt = 0; nt < 8; ++nt)
                    mma16816(acc[mt][nt], a[mt], b[nt]);
        }
        __syncthreads();
    }

    if (OUT_EPI) {
        #pragma unroll
        for (int mt = 0; mt < 2; ++mt) {
            const int r0 = rowg0 + wm * 32 + mt * 16 + (lane >> 2);
            #pragma unroll
            for (int nt = 0; nt < 8; ++nt) {
                const int c = ncol0 + wn * 64 + nt * 8 + (lane & 3) * 2;
                float2 v0 = make_float2(acc[mt][nt][0], acc[mt][nt][1]);
                float2 v1 = make_float2(acc[mt][nt][2], acc[mt][nt][3]);
                const float2 bo = *(const float2*)(bias + c);
                const float2 x0 = *(const float2*)(xres + (size_t)r0 * DIM + c);
                const float2 x1 = *(const float2*)(xres + (size_t)(r0 + 8) * DIM + c);
                v0.x += bo.x + x0.x; v0.y += bo.y + x0.y;
                v1.x += bo.x + x1.x; v1.y += bo.y + x1.y;
                *(float2*)(C + (size_t)r0 * DIM + c) = v0;
                *(float2*)(C + (size_t)(r0 + 8) * DIM + c) = v1;
            }
        }
    } else {
        __nv_bfloat16* dst = (blockIdx.x == 0) ? g_q : (blockIdx.x == 1) ? g_k : g_v;
        #pragma unroll
        for (int mt = 0; mt < 2; ++mt) {
            const int r0 = rowg0 + wm * 32 + mt * 16 + (lane >> 2);
            #pragma unroll
            for (int nt = 0; nt < 8; ++nt) {
                const int c = wn * 64 + nt * 8 + (lane & 3) * 2;
                *(__nv_bfloat162*)(dst + (size_t)r0 * HID + c) =
                    __float22bfloat162_rn(make_float2(acc[mt][nt][0], acc[mt][nt][1]));
                *(__nv_bfloat162*)(dst + (size_t)(r0 + 8) * HID + c) =
                    __float22bfloat162_rn(make_float2(acc[mt][nt][2], acc[mt][nt][3]));
            }
        }
    }
}

#define GEMM_SMEM 65536   // 2 stages x 32 KB

// grid (3, 256): q/k/v = xn @ wqkvT^T   (2 blocks/SM)
__global__ __launch_bounds__(256, 2) void k_qkv_mma() {
    extern __shared__ __align__(1024) char smem[];
    gemm_body<DIM, DIM, 16, false>(g_xn, g_wqkvT, nullptr, nullptr, nullptr, smem);
}
// grid (8, 256): out = q @ Wb_b^T + b_out + x
__global__ __launch_bounds__(256, 2) void k_out_mma(const float* __restrict__ x,
                                                    const float* __restrict__ b_out,
                                                    float* __restrict__ out) {
    extern __shared__ __align__(1024) char smem[];
    const int batch = blockIdx.y >> 5;
    gemm_body<HID, HID, 2, true>(g_q, g_wbT + (size_t)batch * DIM * HID,
                                 out, b_out, x, smem);
}

// ---------------------------------------------------------------------------
// K1: LayerNorm -> bf16, with weight prep fused in the grid tail.
// grid = ROWS + 1536
// ---------------------------------------------------------------------------
__global__ __launch_bounds__(256) void k_ln(const float* __restrict__ x,
                                            const float* __restrict__ gamma,
                                            const float* __restrict__ beta,
                                            const float* __restrict__ wqkv) {
    const int tid = threadIdx.x;
    if (blockIdx.x >= ROWS) {
        const int idx = (blockIdx.x - ROWS) * 256 + tid;   // < 384*1024
        const int n = idx >> 10, k = idx & 1023;
        g_wqkvT[idx] = __float2bfloat16(wqkv[k * 384 + n]);
        return;
    }
    const int row = blockIdx.x;
    const float4 f = ((const float4*)(x + (size_t)row * DIM))[tid];

    float s  = f.x + f.y + f.z + f.w;
    float s2 = fmaf(f.x, f.x, fmaf(f.y, f.y, fmaf(f.z, f.z, f.w * f.w)));
    #pragma unroll
    for (int off = 16; off > 0; off >>= 1) {
        s  += __shfl_xor_sync(0xffffffffu, s,  off);
        s2 += __shfl_xor_sync(0xffffffffu, s2, off);
    }
    __shared__ float red[16];
    const int wid = tid >> 5, lane = tid & 31;
    if (lane == 0) { red[wid] = s; red[8 + wid] = s2; }
    __syncthreads();
    float ts = 0.f, ts2 = 0.f;
    #pragma unroll
    for (int w = 0; w < 8; ++w) { ts += red[w]; ts2 += red[8 + w]; }

    const float mean = ts * (1.0f / DIM);
    const float var  = ts2 * (1.0f / DIM) - mean * mean;
    const float rstd = rsqrtf(var + EPS);

    const float4 g  = ((const float4*)gamma)[tid];
    const float4 be = ((const float4*)beta)[tid];
    __nv_bfloat162 p0, p1;
    p0.x = __float2bfloat16((f.x - mean) * rstd * g.x + be.x);
    p0.y = __float2bfloat16((f.y - mean) * rstd * g.y + be.y);
    p1.x = __float2bfloat16((f.z - mean) * rstd * g.z + be.z);
    p1.y = __float2bfloat16((f.w - mean) * rstd * g.w + be.w);
    __nv_bfloat162* o = (__nv_bfloat162*)(g_xn + (size_t)row * DIM);
    o[tid * 2 + 0] = p0;
    o[tid * 2 + 1] = p1;
}

// ---------------------------------------------------------------------------
// K3: ctx partials via HMMA. pS col-sums now accumulated in registers during
// the fill (each thread owns 8 fixed columns), tree-reduced via 16x128 smem.
// ---------------------------------------------------------------------------
#define CT_KS   0u
#define CT_VS   32768u
#define CT_RED  65536u        // 16*128 floats = 8 KB
#define CT_SMEM 73728

__global__ __launch_bounds__(256, 2) void k_ctx_mma() {
    extern __shared__ __align__(1024) char smem[];
    const uint32_t sb = smem_to_u32(smem);
    const int chunk = blockIdx.x, b = blockIdx.y;
    const int tid = threadIdx.x, lane = tid & 31, wid = tid >> 5;

    const int rbase = b * SEQ + chunk * 128;

    // Fill: k -> exp(k) bf16, v raw copy; col-partials of exp in regs.
    // Thread t: rows (t>>4)+16p, columns (t&15)*8 .. +8 (fixed).
    float colsum[8] = {0.f, 0.f, 0.f, 0.f, 0.f, 0.f, 0.f, 0.f};
    #pragma unroll
    for (int p = 0; p < 8; ++p) {
        const int idx = tid + p * 256;
        const int r = idx >> 4, c = idx & 15;
        const size_t go = (size_t)(rbase + r) * HID + c * 8;
        const uint4 kq = *(const uint4*)(g_k + go);
        const uint32_t kw[4] = {kq.x, kq.y, kq.z, kq.w};
        uint32_t ko[4];
        #pragma unroll
        for (int i = 0; i < 4; ++i) {
            const float2 f = __bfloat1622float2(*(const __nv_bfloat162*)&kw[i]);
            const float e0 = __expf(f.x), e1 = __expf(f.y);
            colsum[i * 2 + 0] += e0;
            colsum[i * 2 + 1] += e1;
            const __nv_bfloat162 e2 = __float22bfloat162_rn(make_float2(e0, e1));
            ko[i] = *(const uint32_t*)&e2;
        }
        const uint32_t o = CSWZ((uint32_t)(r * 256 + c * 16));
        *(uint4*)(smem + CT_KS + o) = make_uint4(ko[0], ko[1], ko[2], ko[3]);
        *(uint4*)(smem + CT_VS + o) = *(const uint4*)(g_v + go);
    }
    {
        float* red = (float*)(smem + CT_RED);
        const int g = tid >> 4, c8 = (tid & 15) * 8;
        #pragma unroll
        for (int i = 0; i < 8; ++i) red[g * 128 + c8 + i] = colsum[i];
    }
    __syncthreads();

    if (tid < 128) {
        const float* red = (const float*)(smem + CT_RED);
        float s = 0.f;
        #pragma unroll
        for (int g = 0; g < 16; ++g) s += red[g * 128 + tid];
        g_pS[chunk * (BATCH * HID) + b * HID + tid] = s;
    }

    const int h  = wid >> 1;
    const int eh = (wid & 1) * 16;

    const int a_n  = ((lane >> 4) * 8) + (lane & 7);
    const int a_d0 = h * 32 + ((lane >> 3) & 1) * 8;
    const int b_n  = (((lane >> 3) & 1) * 8) + (lane & 7);
    const int b_e  = h * 32 + eh + (lane >> 4) * 8;

    float acc[2][2][4];
    #pragma unroll
    for (int mt = 0; mt < 2; ++mt)
        #pragma unroll
        for (int ng = 0; ng < 2; ++ng)
            #pragma unroll
            for (int i = 0; i < 4; ++i) acc[mt][ng][i] = 0.f;

    #pragma unroll
    for (int kt = 0; kt < 8; ++kt) {
        const int n0 = kt * 16;
        uint32_t a[2][4];
        #pragma unroll
        for (int mt = 0; mt < 2; ++mt)
            ldsm_x4_t(a[mt][0], a[mt][1], a[mt][2], a[mt][3],
                      sb + CT_KS + CSWZ((uint32_t)((n0 + a_n) * 256
                                                   + (a_d0 + mt * 16) * 2)));
        uint32_t bb[2][2];
        ldsm_x4_t(bb[0][0], bb[0][1], bb[1][0], bb[1][1],
                  sb + CT_VS + CSWZ((uint32_t)((n0 + b_n) * 256 + b_e * 2)));
        #pragma unroll
        for (int mt = 0; mt < 2; ++mt)
            #pragma unroll
            for (int ng = 0; ng < 2; ++ng)
                mma16816(acc[mt][ng], a[mt], bb[ng]);
    }

    const size_t ob = (size_t)chunk * 32768 + (size_t)b * 4096 + (size_t)h * 1024;
    #pragma unroll
    for (int mt = 0; mt < 2; ++mt) {
        const int d0 = mt * 16 + (lane >> 2);
        #pragma unroll
        for (int ng = 0; ng < 2; ++ng) {
            const int e = eh + ng * 8 + (lane & 3) * 2;
            *(float2*)(g_pctx + ob + (size_t)d0 * 32 + e) =
                make_float2(acc[mt][ng][0], acc[mt][ng][1]);
            *(float2*)(g_pctx + ob + (size_t)(d0 + 8) * 32 + e) =
                make_float2(acc[mt][ng][2], acc[mt][ng][3]);
        }
    }
}

// ---------------------------------------------------------------------------
// K4: partial reduce over chunk-groups (grid (128, 4) — 512 blocks, 8 loads/thr)
// ---------------------------------------------------------------------------
__global__ __launch_bounds__(256) void k_ctx_reduce() {
    const int cg = blockIdx.y;
    const int o  = blockIdx.x * 256 + threadIdx.x;
    float s = 0.f;
    #pragma unroll
    for (int c = 0; c < 8; ++c)
        s += g_pctx[(size_t)(cg * 8 + c) * 32768 + o];
    g_pctx_r[(size_t)cg * 32768 + o] = s;

    if (blockIdx.x == 0) {
        #pragma unroll
        for (int j = 0; j < 4; ++j) {
            const int idx = j * 256 + threadIdx.x;     // < 1024 = BATCH*HID
            float S = 0.f;
            #pragma unroll
            for (int c = 0; c < 8; ++c)
                S += g_pS[(cg * 8 + c) * (BATCH * HID) + idx];
            g_pS_r[cg * (BATCH * HID) + idx] = S;
        }
    }
}

// ---------------------------------------------------------------------------
// K5: Wb_b = Ctx_b @ w_out -> bf16 K-major [b][c][j]
// Folds the final 4-way partial add; softmax scale applied at cv load.
// ---------------------------------------------------------------------------
__global__ __launch_bounds__(256) void k_wb(const float* __restrict__ wout) {
    __shared__ float ctx_s[4096];
    __shared__ float w_s[128][128];
    __shared__ float S_s[128];

    const int tid = threadIdx.x, lane = tid & 31;
    const int b = blockIdx.x >> 3;
    const int c0 = (blockIdx.x & 7) * 128;

    if (tid < 128) {
        float S = 0.f;
        #pragma unroll
        for (int cg = 0; cg < 4; ++cg)
            S += g_pS_r[cg * (BATCH * HID) + b * HID + tid];
        S_s[tid] = SCALE / S;
    }
    #pragma unroll
    for (int i = 0; i < 16; ++i) {
        const int o = i * 256 + tid;
        float s = 0.f;
        #pragma unroll
        for (int cg = 0; cg < 4; ++cg)
            s += g_pctx_r[(size_t)cg * 32768 + b * 4096 + o];
        ctx_s[o] = s;
    }
    #pragma unroll
    for (int p = 0; p < 16; ++p) {
        const int idx = tid + p * 256;
        const int r = idx >> 5, c4 = idx & 31;
        *(float4*)&w_s[r][c4 * 4] = *(const float4*)(wout + r * DIM + c0 + c4 * 4);
    }
    __syncthreads();

    const int h = (tid >> 5) & 3;
    const int j = h * 32 + lane;
    const int cg2 = tid >> 7;

    const float sf = S_s[h * 32 + lane];
    float cv[32];
    #pragma unroll
    for (int e = 0; e < 32; ++e)
        cv[e] = ctx_s[h * 1024 + lane * 32 + e] * sf;

    for (int cc = 0; cc < 64; ++cc) {
        const int c = cg2 * 64 + cc;
        float a = 0.f;
        #pragma unroll
        for (int e = 0; e < 32; ++e)
            a = fmaf(cv[e], w_s[h * 32 + e][c], a);
        g_wbT[((size_t)b * DIM + c0 + c) * HID + j] = __float2bfloat16(a);
    }
}

// ---------------------------------------------------------------------------
extern "C" void kernel_launch(void* const* d_in, const int* in_sizes, int n_in,
                              void* d_out, int out_size) {
    const float* x     = (const float*)d_in[0];
    const float* gamma = (const float*)d_in[1];
    const float* beta  = (const float*)d_in[2];
    const float* wqkv  = (const float*)d_in[3];
    const float* wout  = (const float*)d_in[4];
    const float* bout  = (const float*)d_in[5];
    float* out = (float*)d_out;

    cudaFuncSetAttribute(k_qkv_mma, cudaFuncAttributeMaxDynamicSharedMemorySize, GEMM_SMEM);
    cudaFuncSetAttribute(k_out_mma, cudaFuncAttributeMaxDynamicSharedMemorySize, GEMM_SMEM);
    cudaFuncSetAttribute(k_ctx_mma, cudaFuncAttributeMaxDynamicSharedMemorySize, CT_SMEM);

    k_ln<<<ROWS + 1536, 256>>>(x, gamma, beta, wqkv);
    k_qkv_mma<<<dim3(3, 256), 256, GEMM_SMEM>>>();
    k_ctx_mma<<<dim3(NCHUNK, BATCH), 256, CT_SMEM>>>();
    k_ctx_reduce<<<dim3(128, 4), 256>>>();
    k_wb<<<64, 256>>>(wout);
    k_out_mma<<<dim3(8, 256), 256, GEMM_SMEM>>>(x, bout, out);
}